// round 12
// baseline (speedup 1.0000x reference)
#include <cuda_runtime.h>
#include <cuda_bf16.h>
#include <cstdint>

#define N_TOK 16384
#define D 512
#define K 8192

typedef unsigned int u32;
typedef unsigned long long u64;

constexpr float DECAYC = 0.99f;
constexpr float OMD = (float)(1.0 - 0.99);
constexpr float EPSC = 1e-5f;
constexpr float MARGIN = 0.25f;
#define CAP 32

// output layout (concatenated, float32)
#define OFF_Q    0
#define OFF_LOSS 8388608
#define OFF_IDX  8388609
#define OFF_CS   8404993
#define OFF_EMAW 8413185
#define OFF_W    12607489

// device scratch
__device__ float g_cbnorm[K];
__device__ float g_counts[K];
__device__ float g_cs_pre[K];
__device__ float g_loss;
__device__ float g_sum;
__device__ __nv_bfloat16 g_wb[K * D];     // w * cbnorm, bf16
__device__ int g_ccnt[N_TOK];
__device__ int g_cand[N_TOK * CAP];

__device__ __forceinline__ u64 packkey(float v, int k) {
    u32 b = __float_as_uint(v);
    b = (b & 0x80000000u) ? ~b : (b | 0x80000000u);
    return ((u64)b << 32) | (u32)k;
}
__device__ __forceinline__ float unpackval(u64 key) {
    u32 b = (u32)(key >> 32);
    b = (b & 0x80000000u) ? (b & 0x7FFFFFFFu) : ~b;
    return __uint_as_float(b);
}
__device__ __forceinline__ u32 pack_bf16(float a, float b) {
    __nv_bfloat162 h = __floats2bfloat162_rn(a, b);
    return *(u32*)&h;
}

// ---------------------------------------------------------------------------
// k0 (merged): [0,1024) codebook norms + zero accum; [1024,5120) ema_w*DECAY
// ---------------------------------------------------------------------------
__global__ void __launch_bounds__(256) setup_kernel(const float* __restrict__ w,
                                                    const float* __restrict__ emaw,
                                                    float* __restrict__ out) {
    int bid = blockIdx.x;
    if (bid < 1024) {
        int gid  = bid * 256 + threadIdx.x;
        int wid  = gid >> 5;
        int lane = threadIdx.x & 31;

        const float* row = w + (size_t)wid * D;
        float4 v[4];
        float s = 0.f;
#pragma unroll
        for (int c = 0; c < 4; c++) {
            v[c] = *(const float4*)&row[lane * 4 + c * 128];
            s += v[c].x * v[c].x + v[c].y * v[c].y + v[c].z * v[c].z + v[c].w * v[c].w;
        }
#pragma unroll
        for (int o = 16; o; o >>= 1) s += __shfl_xor_sync(0xffffffffu, s, o);
        float cbn = rsqrtf(s + 1e-12f);
        if (lane == 0) g_cbnorm[wid] = cbn;

#pragma unroll
        for (int c = 0; c < 4; c++) {
            uint2 p;
            p.x = pack_bf16(v[c].x * cbn, v[c].y * cbn);
            p.y = pack_bf16(v[c].z * cbn, v[c].w * cbn);
            *(uint2*)&g_wb[(size_t)wid * D + lane * 4 + c * 128] = p;
        }

        if (gid < K) g_counts[gid] = 0.f;
        if (gid < N_TOK) g_ccnt[gid] = 0;
        if (gid == 0) { g_loss = 0.f; g_sum = 0.f; }
    } else {
        int gid = (bid - 1024) * 256 + threadIdx.x;
        float4 v = *(const float4*)&emaw[gid * 4];
        float* o = out + OFF_EMAW + (size_t)gid * 4;
        o[0] = v.x * DECAYC;
        o[1] = v.y * DECAYC;
        o[2] = v.z * DECAYC;
        o[3] = v.w * DECAYC;
    }
}

// ---------------------------------------------------------------------------
// k1: bf16 mma.sync argmax GEMM + fused rescore/gather tail.
// 128 tokens/CTA, 512 threads (16 warps, 4M x 4N), warp tile 32x64.
// A converted fp32->bf16 in-kernel into swizzled smem (no xconv pass);
// B: 64-d chunks, 3-stage 32KB cp.async pipeline, ONE barrier per chunk
// (wait -> sync -> issue -> compute). Tile epilogue is barrier-free
// (monotone running-max threshold).
// ---------------------------------------------------------------------------
#define BLK_T 128
#define NTHREADS 512
#define SM_BEST 0
#define SM_A    2048
#define SM_B    (SM_A + 131072)               // 133120
#define B_STAGE 32768
#define SMEM_BYTES (SM_B + 3 * B_STAGE)       // 231424
#define GTOT 256                               // 32 tiles * 8 chunks (64d each)

__device__ __forceinline__ void cp16(u32 saddr, const void* gptr) {
    asm volatile("cp.async.cg.shared.global [%0], [%1], 16;\n" :: "r"(saddr), "l"(gptr));
}
__device__ __forceinline__ void cp_commit() { asm volatile("cp.async.commit_group;\n"); }
template <int N>
__device__ __forceinline__ void cp_wait() { asm volatile("cp.async.wait_group %0;\n" :: "n"(N)); }

__device__ __forceinline__ void ldsm4(u32& r0, u32& r1, u32& r2, u32& r3, u32 addr) {
    asm volatile("ldmatrix.sync.aligned.m8n8.x4.shared.b16 {%0,%1,%2,%3}, [%4];\n"
                 : "=r"(r0), "=r"(r1), "=r"(r2), "=r"(r3) : "r"(addr));
}

// B stage offset for (code row 0..255, 16B unit j 0..7); full 128B row
__device__ __forceinline__ u32 b_off(int row, int j) {
    return (u32)(row * 128 + ((j ^ (row & 7)) * 16));
}

__global__ void __launch_bounds__(NTHREADS, 1) mma_argmax_kernel(
        const float* __restrict__ x,
        const float* __restrict__ w,
        float* __restrict__ out) {
    extern __shared__ char dsm[];
    u64* best = (u64*)(dsm + SM_BEST);

    int tid  = threadIdx.x;
    int warp = tid >> 5;
    int lane = tid & 31;
    int r    = lane >> 2;     // 0..7
    int tg   = lane & 3;      // 0..3
    int warpM = warp >> 2;    // 0..3
    int warpN = warp & 3;     // 0..3
    int t0   = blockIdx.x * BLK_T;

    u32 sbase = (u32)__cvta_generic_to_shared(dsm);

    if (tid < BLK_T) best[tid] = packkey(-3e38f, 0);

    // ---- load A: 128 tokens x 512 d fp32 -> bf16, swizzled ----
#pragma unroll
    for (int i = 0; i < 16; i++) {
        int f   = i * NTHREADS + tid;     // 0..8191 16B units (8 bf16 each)
        int row = f >> 6;
        int j   = f & 63;
        const float* src = &x[(size_t)(t0 + row) * D + j * 8];
        float4 a = *(const float4*)src;
        float4 b = *(const float4*)(src + 4);
        uint4 v;
        v.x = pack_bf16(a.x, a.y);
        v.y = pack_bf16(a.z, a.w);
        v.z = pack_bf16(b.x, b.y);
        v.w = pack_bf16(b.z, b.w);
        *(uint4*)(dsm + SM_A + row * 1024 + ((j ^ (row & 7)) * 16)) = v;
    }

    // ---- prime B pipeline: chunks g=0,1 (tile 0, d-chunks 0,1) ----
#pragma unroll
    for (int pg = 0; pg < 2; pg++) {
#pragma unroll
        for (int p = 0; p < 4; p++) {
            int f = p * NTHREADS + tid;   // 0..2047 16B units
            int row = f >> 3, j = f & 7;
            cp16(sbase + SM_B + pg * B_STAGE + b_off(row, j),
                 &g_wb[(size_t)row * D + pg * 64 + j * 8]);
        }
        cp_commit();
    }

    // ldmatrix lane components
    int a_rowl = (lane & 15);             // + warpM*32 + mi*16
    int a_jl   = (lane >> 4);             // + c*8 + s*2
    int a_xor  = (lane & 7);              // (R & 7)
    int b_rowl = warpN * 64 + (lane & 7) + ((lane & 16) ? 8 : 0);
    int b_jl   = ((lane >> 3) & 1);       // + s*2

    float acc[2][8][4];
#pragma unroll
    for (int mi = 0; mi < 2; mi++)
#pragma unroll
        for (int ni = 0; ni < 8; ni++)
#pragma unroll
            for (int e = 0; e < 4; e++) acc[mi][ni][e] = 0.f;

    for (int g = 0; g < GTOT; g++) {
        int c = g & 7;                    // d-chunk within tile (64 d each)
        int kt = (g >> 3) * 256;

        // wait own copies of chunk g (pending {g, g+1} -> leave 1)
        if (g < GTOT - 1) cp_wait<1>();
        else cp_wait<0>();
        __syncthreads();   // ALL threads' chunk-g copies visible; all done with g-1

        // issue chunk g+2 into stage (g+2)%3 == (g-1)%3 (freed by the sync)
        if (g + 2 < GTOT) {
            int ng = g + 2;
            int nkt = (ng >> 3) * 256, nc = ng & 7;
            u32 dst = sbase + SM_B + (ng % 3) * B_STAGE;
#pragma unroll
            for (int p = 0; p < 4; p++) {
                int f = p * NTHREADS + tid;
                int row = f >> 3, j = f & 7;
                cp16(dst + b_off(row, j),
                     &g_wb[(size_t)(nkt + row) * D + nc * 64 + j * 8]);
            }
            cp_commit();
        }

        // ---- compute chunk g (64 d = 4 s-steps) from stage g%3 ----
        u32 bstage = sbase + SM_B + (g % 3) * B_STAGE;
#pragma unroll
        for (int s = 0; s < 4; s++) {
            int aj = c * 8 + s * 2 + a_jl;
            u32 af[2][4];
#pragma unroll
            for (int mi = 0; mi < 2; mi++) {
                int R = warpM * 32 + mi * 16 + a_rowl;
                u32 addr = sbase + SM_A + R * 1024 + ((aj ^ a_xor) * 16);
                ldsm4(af[mi][0], af[mi][1], af[mi][2], af[mi][3], addr);
            }
            int bj = s * 2 + b_jl;
#pragma unroll
            for (int nn = 0; nn < 4; nn++) {
                u32 b0, b1, b2, b3;
                int row = b_rowl + nn * 16;
                ldsm4(b0, b1, b2, b3, bstage + b_off(row, bj));
#pragma unroll
                for (int mi = 0; mi < 2; mi++) {
                    asm volatile(
                        "mma.sync.aligned.m16n8k16.row.col.f32.bf16.bf16.f32 "
                        "{%0,%1,%2,%3}, {%4,%5,%6,%7}, {%8,%9}, {%0,%1,%2,%3};\n"
                        : "+f"(acc[mi][nn*2][0]), "+f"(acc[mi][nn*2][1]),
                          "+f"(acc[mi][nn*2][2]), "+f"(acc[mi][nn*2][3])
                        : "r"(af[mi][0]), "r"(af[mi][1]), "r"(af[mi][2]), "r"(af[mi][3]),
                          "r"(b0), "r"(b1));
                    asm volatile(
                        "mma.sync.aligned.m16n8k16.row.col.f32.bf16.bf16.f32 "
                        "{%0,%1,%2,%3}, {%4,%5,%6,%7}, {%8,%9}, {%0,%1,%2,%3};\n"
                        : "+f"(acc[mi][nn*2+1][0]), "+f"(acc[mi][nn*2+1][1]),
                          "+f"(acc[mi][nn*2+1][2]), "+f"(acc[mi][nn*2+1][3])
                        : "r"(af[mi][0]), "r"(af[mi][1]), "r"(af[mi][2]), "r"(af[mi][3]),
                          "r"(b2), "r"(b3));
                }
            }
        }

        // ---- per-tile epilogue (barrier-free) ----
        if (c == 7) {
#pragma unroll
            for (int mi = 0; mi < 2; mi++) {
#pragma unroll
                for (int h = 0; h < 2; h++) {
                    // local fold over this warp's 64 codes for the token
                    float bv = -3e38f; int bk = 0;
#pragma unroll
                    for (int ni = 0; ni < 8; ni++) {
                        int k0 = kt + warpN * 64 + ni * 8 + 2 * tg;
                        float v0 = acc[mi][ni][h * 2 + 0];
                        float v1 = acc[mi][ni][h * 2 + 1];
                        if (v0 > bv) { bv = v0; bk = k0; }
                        if (v1 > bv) { bv = v1; bk = k0 + 1; }
                    }
                    u64 key = packkey(bv, bk);
                    u64 o1 = __shfl_xor_sync(0xffffffffu, key, 1);
                    if (o1 > key) key = o1;
                    u64 o2 = __shfl_xor_sync(0xffffffffu, key, 2);
                    if (o2 > key) key = o2;
                    // key = warp-wide max over its 64 codes (same in all 4 tg)

                    int lt = warpM * 32 + mi * 16 + h * 8 + r;
                    int token = t0 + lt;
                    // threshold: monotone-below-final running max (stale read OK)
                    float known = unpackval(best[lt]);
                    float wmax  = unpackval(key);
                    float thr = (known > wmax ? known : wmax) - MARGIN;
#pragma unroll
                    for (int ni = 0; ni < 8; ni++) {
                        int k0 = kt + warpN * 64 + ni * 8 + 2 * tg;
#pragma unroll
                        for (int e = 0; e < 2; e++) {
                            if (acc[mi][ni][h * 2 + e] >= thr) {
                                int pos = atomicAdd(&g_ccnt[token], 1);
                                if (pos < CAP) g_cand[token * CAP + pos] = k0 + e;
                            }
                        }
                    }
                    if (tg == 0) atomicMax(&best[lt], key);
                }
            }
            // reset accumulators for next tile
#pragma unroll
            for (int mi = 0; mi < 2; mi++)
#pragma unroll
                for (int ni = 0; ni < 8; ni++)
#pragma unroll
                    for (int e = 0; e < 4; e++) acc[mi][ni][e] = 0.f;
        }
    }

    // =======================================================================
    // fused tail: exact fp32 rescore + gather/loss/emaw, 8 tokens per warp
    // =======================================================================
    __syncthreads();
    float* out_idx = out + OFF_IDX;

    for (int i = 0; i < 8; i++) {
        int lt = warp * 8 + i;
        int token = t0 + lt;
        const float* xr = x + (size_t)token * D;

        float4 xv[4];
#pragma unroll
        for (int c = 0; c < 4; c++)
            xv[c] = *(const float4*)&xr[lane * 4 + c * 128];

        int cnt = g_ccnt[token];
        float bestv = -3e38f;
        int   bk    = K;

        if (cnt <= CAP) {
            for (int j = 0; j < cnt; j++) {
                int k = g_cand[token * CAP + j];
                float s = 0.f;
#pragma unroll
                for (int c = 0; c < 4; c++) {
                    float4 wv = *(const float4*)&w[(size_t)k * D + lane * 4 + c * 128];
                    s += xv[c].x * wv.x + xv[c].y * wv.y + xv[c].z * wv.z + xv[c].w * wv.w;
                }
#pragma unroll
                for (int o = 16; o; o >>= 1) s += __shfl_xor_sync(0xffffffffu, s, o);
                s *= g_cbnorm[k];
                if (s > bestv || (s == bestv && k < bk)) { bestv = s; bk = k; }
            }
        } else {
            // overflow fallback: exact scan of all codes
            for (int k = 0; k < K; k++) {
                float s = 0.f;
#pragma unroll
                for (int c = 0; c < 4; c++) {
                    float4 wv = *(const float4*)&w[(size_t)k * D + lane * 4 + c * 128];
                    s += xv[c].x * wv.x + xv[c].y * wv.y + xv[c].z * wv.z + xv[c].w * wv.w;
                }
#pragma unroll
                for (int o = 16; o; o >>= 1) s += __shfl_xor_sync(0xffffffffu, s, o);
                s *= g_cbnorm[k];
                if (s > bestv || (s == bestv && k < bk)) { bestv = s; bk = k; }
            }
        }

        // gather + straight-through + loss + emaw scatter
        const float* wr = w + (size_t)bk * D;
        float* q    = out + OFF_Q + (size_t)token * D;
        float* emaw = out + OFF_EMAW + (size_t)bk * D;

        float lsum = 0.f;
#pragma unroll
        for (int c = 0; c < 4; c++) {
            int d = lane * 4 + c * 128;
            float4 wv = *(const float4*)&wr[d];
            float4 qv;
            qv.x = xv[c].x + (wv.x - xv[c].x);
            qv.y = xv[c].y + (wv.y - xv[c].y);
            qv.z = xv[c].z + (wv.z - xv[c].z);
            qv.w = xv[c].w + (wv.w - xv[c].w);
            *(float4*)&q[d] = qv;
            float d0 = wv.x - xv[c].x, d1 = wv.y - xv[c].y;
            float d2 = wv.z - xv[c].z, d3 = wv.w - xv[c].w;
            lsum += d0 * d0 + d1 * d1 + d2 * d2 + d3 * d3;
            atomicAdd(&emaw[d + 0], OMD * xv[c].x);
            atomicAdd(&emaw[d + 1], OMD * xv[c].y);
            atomicAdd(&emaw[d + 2], OMD * xv[c].z);
            atomicAdd(&emaw[d + 3], OMD * xv[c].w);
        }
#pragma unroll
        for (int o = 16; o; o >>= 1) lsum += __shfl_xor_sync(0xffffffffu, lsum, o);
        if (lane == 0) {
            atomicAdd(&g_loss, lsum);
            out_idx[token] = (float)bk;
            atomicAdd(&g_counts[bk], 1.0f);
        }
    }
}

// ---------------------------------------------------------------------------
// k4: cluster-size EMA pre-values + global sum
// ---------------------------------------------------------------------------
__global__ void __launch_bounds__(256) cs_kernel(const float* __restrict__ ecs) {
    __shared__ float red[256];
    int k = blockIdx.x * 256 + threadIdx.x;
    float v = ecs[k] * DECAYC + OMD * g_counts[k];
    g_cs_pre[k] = v;
    red[threadIdx.x] = v;
    __syncthreads();
    for (int s = 128; s; s >>= 1) {
        if (threadIdx.x < s) red[threadIdx.x] += red[threadIdx.x + s];
        __syncthreads();
    }
    if (threadIdx.x == 0) atomicAdd(&g_sum, red[0]);
}

// ---------------------------------------------------------------------------
// k5: finalize new_cs, new_weight, loss mean
// ---------------------------------------------------------------------------
__global__ void __launch_bounds__(256) finalize_kernel(float* __restrict__ out) {
    int gid = blockIdx.x * 256 + threadIdx.x;
    if (gid == 0) out[OFF_LOSS] = g_loss * (1.0f / ((float)N_TOK * (float)D));

    int k  = gid >> 7;
    int d4 = gid & 127;
    float n  = g_sum;
    float cs = (g_cs_pre[k] + EPSC) / (n + (float)K * EPSC) * n;
    if (d4 == 0) out[OFF_CS + k] = cs;

    size_t base = (size_t)k * D + d4 * 4;
#pragma unroll
    for (int q = 0; q < 4; q++) {
        float e = out[OFF_EMAW + base + q];
        out[OFF_W + base + q] = e / cs;
    }
}

// ---------------------------------------------------------------------------
extern "C" void kernel_launch(void* const* d_in, const int* in_sizes, int n_in,
                              void* d_out, int out_size) {
    const float* x    = (const float*)d_in[0];
    const float* w    = (const float*)d_in[1];
    const float* ecs  = (const float*)d_in[2];
    const float* emaw = (const float*)d_in[3];
    float* out = (float*)d_out;

    cudaFuncSetAttribute(mma_argmax_kernel,
                         cudaFuncAttributeMaxDynamicSharedMemorySize, SMEM_BYTES);

    setup_kernel<<<5120, 256>>>(w, emaw, out);
    mma_argmax_kernel<<<N_TOK / BLK_T, NTHREADS, SMEM_BYTES>>>(x, w, out);
    cs_kernel<<<K / 256, 256>>>(ecs);
    finalize_kernel<<<(K * D / 4) / 256, 256>>>(out);
}

// round 13
// speedup vs baseline: 7.1037x; 7.1037x over previous
#include <cuda_runtime.h>
#include <cuda_bf16.h>
#include <cstdint>

#define N_TOK 16384
#define D 512
#define K 8192

typedef unsigned int u32;
typedef unsigned long long u64;

constexpr float DECAYC = 0.99f;
constexpr float OMD = (float)(1.0 - 0.99);
constexpr float EPSC = 1e-5f;
constexpr float MARGIN = 0.25f;
#define CAP 32

// output layout (concatenated, float32)
#define OFF_Q    0
#define OFF_LOSS 8388608
#define OFF_IDX  8388609
#define OFF_CS   8404993
#define OFF_EMAW 8413185
#define OFF_W    12607489

// device scratch
__device__ float g_cbnorm[K];
__device__ float g_counts[K];
__device__ float g_cs_pre[K];
__device__ float g_loss;
__device__ float g_sum;
__device__ __nv_bfloat16 g_wb[K * D];     // w * cbnorm, bf16
__device__ int g_ccnt[N_TOK];
__device__ int g_cand[N_TOK * CAP];

__device__ __forceinline__ u64 packkey(float v, int k) {
    u32 b = __float_as_uint(v);
    b = (b & 0x80000000u) ? ~b : (b | 0x80000000u);
    return ((u64)b << 32) | (u32)k;
}
__device__ __forceinline__ float unpackval(u64 key) {
    u32 b = (u32)(key >> 32);
    b = (b & 0x80000000u) ? (b & 0x7FFFFFFFu) : ~b;
    return __uint_as_float(b);
}
__device__ __forceinline__ u32 pack_bf16(float a, float b) {
    __nv_bfloat162 h = __floats2bfloat162_rn(a, b);
    return *(u32*)&h;
}

// ---------------------------------------------------------------------------
// k0 (merged): [0,1024) codebook norms + zero accum; [1024,5120) ema_w*DECAY
// ---------------------------------------------------------------------------
__global__ void __launch_bounds__(256) setup_kernel(const float* __restrict__ w,
                                                    const float* __restrict__ emaw,
                                                    float* __restrict__ out) {
    int bid = blockIdx.x;
    if (bid < 1024) {
        int gid  = bid * 256 + threadIdx.x;
        int wid  = gid >> 5;
        int lane = threadIdx.x & 31;

        const float* row = w + (size_t)wid * D;
        float4 v[4];
        float s = 0.f;
#pragma unroll
        for (int c = 0; c < 4; c++) {
            v[c] = *(const float4*)&row[lane * 4 + c * 128];
            s += v[c].x * v[c].x + v[c].y * v[c].y + v[c].z * v[c].z + v[c].w * v[c].w;
        }
#pragma unroll
        for (int o = 16; o; o >>= 1) s += __shfl_xor_sync(0xffffffffu, s, o);
        float cbn = rsqrtf(s + 1e-12f);
        if (lane == 0) g_cbnorm[wid] = cbn;

#pragma unroll
        for (int c = 0; c < 4; c++) {
            uint2 p;
            p.x = pack_bf16(v[c].x * cbn, v[c].y * cbn);
            p.y = pack_bf16(v[c].z * cbn, v[c].w * cbn);
            *(uint2*)&g_wb[(size_t)wid * D + lane * 4 + c * 128] = p;
        }

        if (gid < K) g_counts[gid] = 0.f;
        if (gid < N_TOK) g_ccnt[gid] = 0;
        if (gid == 0) { g_loss = 0.f; g_sum = 0.f; }
    } else {
        int gid = (bid - 1024) * 256 + threadIdx.x;
        float4 v = *(const float4*)&emaw[gid * 4];
        float* o = out + OFF_EMAW + (size_t)gid * 4;
        o[0] = v.x * DECAYC;
        o[1] = v.y * DECAYC;
        o[2] = v.z * DECAYC;
        o[3] = v.w * DECAYC;
    }
}

// ---------------------------------------------------------------------------
// k1: bf16 mma.sync argmax GEMM + fused rescore/gather tail.
// 128 tokens/CTA, 512 threads (16 warps, 4M x 4N), warp tile 32x64.
// A converted fp32->bf16 in-kernel into swizzled smem (no xconv pass);
// B: 64-d chunks, 3-stage 32KB cp.async pipeline, ONE barrier per chunk
// (wait -> sync -> issue -> compute). Barriered per-tile epilogue
// (atomicMax -> sync -> collect) — the R10-proven candidate logic.
// ---------------------------------------------------------------------------
#define BLK_T 128
#define NTHREADS 512
#define SM_BEST 0
#define SM_A    2048
#define SM_B    (SM_A + 131072)               // 133120
#define B_STAGE 32768
#define SMEM_BYTES (SM_B + 3 * B_STAGE)       // 231424
#define GTOT 256                               // 32 tiles * 8 chunks (64d each)

__device__ __forceinline__ void cp16(u32 saddr, const void* gptr) {
    asm volatile("cp.async.cg.shared.global [%0], [%1], 16;\n" :: "r"(saddr), "l"(gptr));
}
__device__ __forceinline__ void cp_commit() { asm volatile("cp.async.commit_group;\n"); }
template <int N>
__device__ __forceinline__ void cp_wait() { asm volatile("cp.async.wait_group %0;\n" :: "n"(N)); }

__device__ __forceinline__ void ldsm4(u32& r0, u32& r1, u32& r2, u32& r3, u32 addr) {
    asm volatile("ldmatrix.sync.aligned.m8n8.x4.shared.b16 {%0,%1,%2,%3}, [%4];\n"
                 : "=r"(r0), "=r"(r1), "=r"(r2), "=r"(r3) : "r"(addr));
}

// B stage offset for (code row 0..255, 16B unit j 0..7); full 128B row
__device__ __forceinline__ u32 b_off(int row, int j) {
    return (u32)(row * 128 + ((j ^ (row & 7)) * 16));
}

__global__ void __launch_bounds__(NTHREADS, 1) mma_argmax_kernel(
        const float* __restrict__ x,
        const float* __restrict__ w,
        float* __restrict__ out) {
    extern __shared__ char dsm[];
    u64* best = (u64*)(dsm + SM_BEST);

    int tid  = threadIdx.x;
    int warp = tid >> 5;
    int lane = tid & 31;
    int r    = lane >> 2;     // 0..7
    int tg   = lane & 3;      // 0..3
    int warpM = warp >> 2;    // 0..3
    int warpN = warp & 3;     // 0..3
    int t0   = blockIdx.x * BLK_T;

    u32 sbase = (u32)__cvta_generic_to_shared(dsm);

    if (tid < BLK_T) best[tid] = packkey(-3e38f, 0);

    // ---- load A: 128 tokens x 512 d fp32 -> bf16, swizzled ----
#pragma unroll
    for (int i = 0; i < 16; i++) {
        int f   = i * NTHREADS + tid;     // 0..8191 16B units (8 bf16 each)
        int row = f >> 6;
        int j   = f & 63;
        const float* src = &x[(size_t)(t0 + row) * D + j * 8];
        float4 a = *(const float4*)src;
        float4 b = *(const float4*)(src + 4);
        uint4 v;
        v.x = pack_bf16(a.x, a.y);
        v.y = pack_bf16(a.z, a.w);
        v.z = pack_bf16(b.x, b.y);
        v.w = pack_bf16(b.z, b.w);
        *(uint4*)(dsm + SM_A + row * 1024 + ((j ^ (row & 7)) * 16)) = v;
    }

    // ---- prime B pipeline: chunks g=0,1 (tile 0, d-chunks 0,1) ----
#pragma unroll
    for (int pg = 0; pg < 2; pg++) {
#pragma unroll
        for (int p = 0; p < 4; p++) {
            int f = p * NTHREADS + tid;   // 0..2047 16B units
            int row = f >> 3, j = f & 7;
            cp16(sbase + SM_B + pg * B_STAGE + b_off(row, j),
                 &g_wb[(size_t)row * D + pg * 64 + j * 8]);
        }
        cp_commit();
    }

    // ldmatrix lane components
    int a_rowl = (lane & 15);             // + warpM*32 + mi*16
    int a_jl   = (lane >> 4);             // + c*8 + s*2
    int a_xor  = (lane & 7);              // (R & 7)
    int b_rowl = warpN * 64 + (lane & 7) + ((lane & 16) ? 8 : 0);
    int b_jl   = ((lane >> 3) & 1);       // + s*2

    float acc[2][8][4];
#pragma unroll
    for (int mi = 0; mi < 2; mi++)
#pragma unroll
        for (int ni = 0; ni < 8; ni++)
#pragma unroll
            for (int e = 0; e < 4; e++) acc[mi][ni][e] = 0.f;

    for (int g = 0; g < GTOT; g++) {
        int c = g & 7;                    // d-chunk within tile (64 d each)
        int kt = (g >> 3) * 256;

        // wait own copies of chunk g (pending {g, g+1} -> leave 1)
        if (g < GTOT - 1) cp_wait<1>();
        else cp_wait<0>();
        __syncthreads();   // ALL threads' chunk-g copies visible; all done with g-1

        // issue chunk g+2 into stage (g+2)%3 == (g-1)%3 (freed by the sync)
        if (g + 2 < GTOT) {
            int ng = g + 2;
            int nkt = (ng >> 3) * 256, nc = ng & 7;
            u32 dst = sbase + SM_B + (ng % 3) * B_STAGE;
#pragma unroll
            for (int p = 0; p < 4; p++) {
                int f = p * NTHREADS + tid;
                int row = f >> 3, j = f & 7;
                cp16(dst + b_off(row, j),
                     &g_wb[(size_t)(nkt + row) * D + nc * 64 + j * 8]);
            }
            cp_commit();
        }

        // ---- compute chunk g (64 d = 4 s-steps) from stage g%3 ----
        u32 bstage = sbase + SM_B + (g % 3) * B_STAGE;
#pragma unroll
        for (int s = 0; s < 4; s++) {
            int aj = c * 8 + s * 2 + a_jl;
            u32 af[2][4];
#pragma unroll
            for (int mi = 0; mi < 2; mi++) {
                int R = warpM * 32 + mi * 16 + a_rowl;
                u32 addr = sbase + SM_A + R * 1024 + ((aj ^ a_xor) * 16);
                ldsm4(af[mi][0], af[mi][1], af[mi][2], af[mi][3], addr);
            }
            int bj = s * 2 + b_jl;
#pragma unroll
            for (int nn = 0; nn < 4; nn++) {
                u32 b0, b1, b2, b3;
                int row = b_rowl + nn * 16;
                ldsm4(b0, b1, b2, b3, bstage + b_off(row, bj));
#pragma unroll
                for (int mi = 0; mi < 2; mi++) {
                    asm volatile(
                        "mma.sync.aligned.m16n8k16.row.col.f32.bf16.bf16.f32 "
                        "{%0,%1,%2,%3}, {%4,%5,%6,%7}, {%8,%9}, {%0,%1,%2,%3};\n"
                        : "+f"(acc[mi][nn*2][0]), "+f"(acc[mi][nn*2][1]),
                          "+f"(acc[mi][nn*2][2]), "+f"(acc[mi][nn*2][3])
                        : "r"(af[mi][0]), "r"(af[mi][1]), "r"(af[mi][2]), "r"(af[mi][3]),
                          "r"(b0), "r"(b1));
                    asm volatile(
                        "mma.sync.aligned.m16n8k16.row.col.f32.bf16.bf16.f32 "
                        "{%0,%1,%2,%3}, {%4,%5,%6,%7}, {%8,%9}, {%0,%1,%2,%3};\n"
                        : "+f"(acc[mi][nn*2+1][0]), "+f"(acc[mi][nn*2+1][1]),
                          "+f"(acc[mi][nn*2+1][2]), "+f"(acc[mi][nn*2+1][3])
                        : "r"(af[mi][0]), "r"(af[mi][1]), "r"(af[mi][2]), "r"(af[mi][3]),
                          "r"(b2), "r"(b3));
                }
            }
        }

        // ---- per-tile epilogue (after last d-chunk of this code tile) ----
        if (c == 7) {
            // fold: running max per token -> atomicMax into smem best
#pragma unroll
            for (int mi = 0; mi < 2; mi++) {
#pragma unroll
                for (int h = 0; h < 2; h++) {
                    float bv = -3e38f; int bk = 0;
#pragma unroll
                    for (int ni = 0; ni < 8; ni++) {
                        int k0 = kt + warpN * 64 + ni * 8 + 2 * tg;
                        float v0 = acc[mi][ni][h * 2 + 0];
                        float v1 = acc[mi][ni][h * 2 + 1];
                        if (v0 > bv) { bv = v0; bk = k0; }
                        if (v1 > bv) { bv = v1; bk = k0 + 1; }
                    }
                    u64 key = packkey(bv, bk);
                    u64 o1 = __shfl_xor_sync(0xffffffffu, key, 1);
                    if (o1 > key) key = o1;
                    u64 o2 = __shfl_xor_sync(0xffffffffu, key, 2);
                    if (o2 > key) key = o2;
                    if (tg == 0)
                        atomicMax(&best[warpM * 32 + mi * 16 + h * 8 + r], key);
                }
            }
            __syncthreads();
            // candidate collection vs running max (global list)
#pragma unroll
            for (int mi = 0; mi < 2; mi++) {
#pragma unroll
                for (int h = 0; h < 2; h++) {
                    int lt = warpM * 32 + mi * 16 + h * 8 + r;
                    float thr = unpackval(best[lt]) - MARGIN;
                    int token = t0 + lt;
#pragma unroll
                    for (int ni = 0; ni < 8; ni++) {
                        int k0 = kt + warpN * 64 + ni * 8 + 2 * tg;
#pragma unroll
                        for (int e = 0; e < 2; e++) {
                            if (acc[mi][ni][h * 2 + e] >= thr) {
                                int pos = atomicAdd(&g_ccnt[token], 1);
                                if (pos < CAP) g_cand[token * CAP + pos] = k0 + e;
                            }
                        }
                    }
                }
            }
            // reset accumulators for next tile
#pragma unroll
            for (int mi = 0; mi < 2; mi++)
#pragma unroll
                for (int ni = 0; ni < 8; ni++)
#pragma unroll
                    for (int e = 0; e < 4; e++) acc[mi][ni][e] = 0.f;
        }
    }

    // =======================================================================
    // fused tail: exact fp32 rescore + gather/loss/emaw, 8 tokens per warp
    // =======================================================================
    __syncthreads();
    float* out_idx = out + OFF_IDX;

    for (int i = 0; i < 8; i++) {
        int lt = warp * 8 + i;
        int token = t0 + lt;
        const float* xr = x + (size_t)token * D;

        float4 xv[4];
#pragma unroll
        for (int c = 0; c < 4; c++)
            xv[c] = *(const float4*)&xr[lane * 4 + c * 128];

        int cnt = g_ccnt[token];
        float bestv = -3e38f;
        int   bk    = K;

        if (cnt <= CAP) {
            for (int j = 0; j < cnt; j++) {
                int k = g_cand[token * CAP + j];
                float s = 0.f;
#pragma unroll
                for (int c = 0; c < 4; c++) {
                    float4 wv = *(const float4*)&w[(size_t)k * D + lane * 4 + c * 128];
                    s += xv[c].x * wv.x + xv[c].y * wv.y + xv[c].z * wv.z + xv[c].w * wv.w;
                }
#pragma unroll
                for (int o = 16; o; o >>= 1) s += __shfl_xor_sync(0xffffffffu, s, o);
                s *= g_cbnorm[k];
                if (s > bestv || (s == bestv && k < bk)) { bestv = s; bk = k; }
            }
        } else {
            // overflow fallback: exact scan of all codes
            for (int k = 0; k < K; k++) {
                float s = 0.f;
#pragma unroll
                for (int c = 0; c < 4; c++) {
                    float4 wv = *(const float4*)&w[(size_t)k * D + lane * 4 + c * 128];
                    s += xv[c].x * wv.x + xv[c].y * wv.y + xv[c].z * wv.z + xv[c].w * wv.w;
                }
#pragma unroll
                for (int o = 16; o; o >>= 1) s += __shfl_xor_sync(0xffffffffu, s, o);
                s *= g_cbnorm[k];
                if (s > bestv || (s == bestv && k < bk)) { bestv = s; bk = k; }
            }
        }

        // gather + straight-through + loss + emaw scatter
        const float* wr = w + (size_t)bk * D;
        float* q    = out + OFF_Q + (size_t)token * D;
        float* emaw = out + OFF_EMAW + (size_t)bk * D;

        float lsum = 0.f;
#pragma unroll
        for (int c = 0; c < 4; c++) {
            int d = lane * 4 + c * 128;
            float4 wv = *(const float4*)&wr[d];
            float4 qv;
            qv.x = xv[c].x + (wv.x - xv[c].x);
            qv.y = xv[c].y + (wv.y - xv[c].y);
            qv.z = xv[c].z + (wv.z - xv[c].z);
            qv.w = xv[c].w + (wv.w - xv[c].w);
            *(float4*)&q[d] = qv;
            float d0 = wv.x - xv[c].x, d1 = wv.y - xv[c].y;
            float d2 = wv.z - xv[c].z, d3 = wv.w - xv[c].w;
            lsum += d0 * d0 + d1 * d1 + d2 * d2 + d3 * d3;
            atomicAdd(&emaw[d + 0], OMD * xv[c].x);
            atomicAdd(&emaw[d + 1], OMD * xv[c].y);
            atomicAdd(&emaw[d + 2], OMD * xv[c].z);
            atomicAdd(&emaw[d + 3], OMD * xv[c].w);
        }
#pragma unroll
        for (int o = 16; o; o >>= 1) lsum += __shfl_xor_sync(0xffffffffu, lsum, o);
        if (lane == 0) {
            atomicAdd(&g_loss, lsum);
            out_idx[token] = (float)bk;
            atomicAdd(&g_counts[bk], 1.0f);
        }
    }
}

// ---------------------------------------------------------------------------
// k4: cluster-size EMA pre-values + global sum
// ---------------------------------------------------------------------------
__global__ void __launch_bounds__(256) cs_kernel(const float* __restrict__ ecs) {
    __shared__ float red[256];
    int k = blockIdx.x * 256 + threadIdx.x;
    float v = ecs[k] * DECAYC + OMD * g_counts[k];
    g_cs_pre[k] = v;
    red[threadIdx.x] = v;
    __syncthreads();
    for (int s = 128; s; s >>= 1) {
        if (threadIdx.x < s) red[threadIdx.x] += red[threadIdx.x + s];
        __syncthreads();
    }
    if (threadIdx.x == 0) atomicAdd(&g_sum, red[0]);
}

// ---------------------------------------------------------------------------
// k5: finalize new_cs, new_weight, loss mean
// ---------------------------------------------------------------------------
__global__ void __launch_bounds__(256) finalize_kernel(float* __restrict__ out) {
    int gid = blockIdx.x * 256 + threadIdx.x;
    if (gid == 0) out[OFF_LOSS] = g_loss * (1.0f / ((float)N_TOK * (float)D));

    int k  = gid >> 7;
    int d4 = gid & 127;
    float n  = g_sum;
    float cs = (g_cs_pre[k] + EPSC) / (n + (float)K * EPSC) * n;
    if (d4 == 0) out[OFF_CS + k] = cs;

    size_t base = (size_t)k * D + d4 * 4;
#pragma unroll
    for (int q = 0; q < 4; q++) {
        float e = out[OFF_EMAW + base + q];
        out[OFF_W + base + q] = e / cs;
    }
}

// ---------------------------------------------------------------------------
extern "C" void kernel_launch(void* const* d_in, const int* in_sizes, int n_in,
                              void* d_out, int out_size) {
    const float* x    = (const float*)d_in[0];
    const float* w    = (const float*)d_in[1];
    const float* ecs  = (const float*)d_in[2];
    const float* emaw = (const float*)d_in[3];
    float* out = (float*)d_out;

    cudaFuncSetAttribute(mma_argmax_kernel,
                         cudaFuncAttributeMaxDynamicSharedMemorySize, SMEM_BYTES);

    setup_kernel<<<5120, 256>>>(w, emaw, out);
    mma_argmax_kernel<<<N_TOK / BLK_T, NTHREADS, SMEM_BYTES>>>(x, w, out);
    cs_kernel<<<K / 256, 256>>>(ecs);
    finalize_kernel<<<(K * D / 4) / 256, 256>>>(out);
}

// round 14
// speedup vs baseline: 7.9869x; 1.1243x over previous
#include <cuda_runtime.h>
#include <cuda_bf16.h>
#include <cstdint>

#define N_TOK 16384
#define D 512
#define K 8192

typedef unsigned int u32;
typedef unsigned long long u64;

constexpr float DECAYC = 0.99f;
constexpr float OMD = (float)(1.0 - 0.99);
constexpr float EPSC = 1e-5f;
constexpr float MARGIN = 0.15f;
#define CAP 32

// output layout (concatenated, float32)
#define OFF_Q    0
#define OFF_LOSS 8388608
#define OFF_IDX  8388609
#define OFF_CS   8404993
#define OFF_EMAW 8413185
#define OFF_W    12607489

// device scratch
__device__ float g_cbnorm[K];
__device__ float g_counts[K];
__device__ float g_cs_pre[K];
__device__ float g_loss;
__device__ float g_sum;
__device__ __nv_bfloat16 g_wb[K * D];     // w * cbnorm, bf16
__device__ int g_ccnt[N_TOK];
__device__ int g_cand[N_TOK * CAP];

__device__ __forceinline__ u64 packkey(float v, int k) {
    u32 b = __float_as_uint(v);
    b = (b & 0x80000000u) ? ~b : (b | 0x80000000u);
    return ((u64)b << 32) | (u32)k;
}
__device__ __forceinline__ float unpackval(u64 key) {
    u32 b = (u32)(key >> 32);
    b = (b & 0x80000000u) ? (b & 0x7FFFFFFFu) : ~b;
    return __uint_as_float(b);
}
__device__ __forceinline__ u32 pack_bf16(float a, float b) {
    __nv_bfloat162 h = __floats2bfloat162_rn(a, b);
    return *(u32*)&h;
}

// ---------------------------------------------------------------------------
// k0 (merged): [0,1024) codebook norms + zero accum; [1024,5120) ema_w*DECAY
// ---------------------------------------------------------------------------
__global__ void __launch_bounds__(256) setup_kernel(const float* __restrict__ w,
                                                    const float* __restrict__ emaw,
                                                    float* __restrict__ out) {
    int bid = blockIdx.x;
    if (bid < 1024) {
        int gid  = bid * 256 + threadIdx.x;
        int wid  = gid >> 5;
        int lane = threadIdx.x & 31;

        const float* row = w + (size_t)wid * D;
        float4 v[4];
        float s = 0.f;
#pragma unroll
        for (int c = 0; c < 4; c++) {
            v[c] = *(const float4*)&row[lane * 4 + c * 128];
            s += v[c].x * v[c].x + v[c].y * v[c].y + v[c].z * v[c].z + v[c].w * v[c].w;
        }
#pragma unroll
        for (int o = 16; o; o >>= 1) s += __shfl_xor_sync(0xffffffffu, s, o);
        float cbn = rsqrtf(s + 1e-12f);
        if (lane == 0) g_cbnorm[wid] = cbn;

#pragma unroll
        for (int c = 0; c < 4; c++) {
            uint2 p;
            p.x = pack_bf16(v[c].x * cbn, v[c].y * cbn);
            p.y = pack_bf16(v[c].z * cbn, v[c].w * cbn);
            *(uint2*)&g_wb[(size_t)wid * D + lane * 4 + c * 128] = p;
        }

        if (gid < K) g_counts[gid] = 0.f;
        if (gid < N_TOK) g_ccnt[gid] = 0;
        if (gid == 0) { g_loss = 0.f; g_sum = 0.f; }
    } else {
        int gid = (bid - 1024) * 256 + threadIdx.x;
        float4 v = *(const float4*)&emaw[gid * 4];
        float* o = out + OFF_EMAW + (size_t)gid * 4;
        o[0] = v.x * DECAYC;
        o[1] = v.y * DECAYC;
        o[2] = v.z * DECAYC;
        o[3] = v.w * DECAYC;
    }
}

// ---------------------------------------------------------------------------
// k1: bf16 mma.sync argmax GEMM + fused rescore/gather tail.
// 128 tokens/CTA, 512 threads (16 warps, 4M x 4N), warp tile 32x64.
// A fp32->bf16 in-kernel into swizzled smem. B: 64-d chunks, 3-stage 32KB
// cp.async, ONE barrier per chunk (wait -> sync -> collect(prev tile) ->
// compute -> issue). Tile-start MMA uses c=0 operand (no acc reset needed),
// so collect can run one chunk late under the normal barrier.
// ---------------------------------------------------------------------------
#define BLK_T 128
#define NTHREADS 512
#define SM_BEST 0
#define SM_A    2048
#define SM_B    (SM_A + 131072)               // 133120
#define B_STAGE 32768
#define SMEM_BYTES (SM_B + 3 * B_STAGE)       // 231424
#define GTOT 256                               // 32 tiles * 8 chunks (64d each)

__device__ __forceinline__ void cp16(u32 saddr, const void* gptr) {
    asm volatile("cp.async.cg.shared.global [%0], [%1], 16;\n" :: "r"(saddr), "l"(gptr));
}
__device__ __forceinline__ void cp_commit() { asm volatile("cp.async.commit_group;\n"); }
template <int N>
__device__ __forceinline__ void cp_wait() { asm volatile("cp.async.wait_group %0;\n" :: "n"(N)); }

__device__ __forceinline__ void ldsm4(u32& r0, u32& r1, u32& r2, u32& r3, u32 addr) {
    asm volatile("ldmatrix.sync.aligned.m8n8.x4.shared.b16 {%0,%1,%2,%3}, [%4];\n"
                 : "=r"(r0), "=r"(r1), "=r"(r2), "=r"(r3) : "r"(addr));
}

__device__ __forceinline__ void mma_acc(float* d, const u32* a, u32 b0, u32 b1) {
    asm volatile(
        "mma.sync.aligned.m16n8k16.row.col.f32.bf16.bf16.f32 "
        "{%0,%1,%2,%3}, {%4,%5,%6,%7}, {%8,%9}, {%0,%1,%2,%3};\n"
        : "+f"(d[0]), "+f"(d[1]), "+f"(d[2]), "+f"(d[3])
        : "r"(a[0]), "r"(a[1]), "r"(a[2]), "r"(a[3]), "r"(b0), "r"(b1));
}
// overwrite variant: c operand = 0, d written (no prior acc read)
__device__ __forceinline__ void mma_zero(float* d, const u32* a, u32 b0, u32 b1) {
    float z = 0.f;
    asm volatile(
        "mma.sync.aligned.m16n8k16.row.col.f32.bf16.bf16.f32 "
        "{%0,%1,%2,%3}, {%4,%5,%6,%7}, {%8,%9}, {%10,%10,%10,%10};\n"
        : "=f"(d[0]), "=f"(d[1]), "=f"(d[2]), "=f"(d[3])
        : "r"(a[0]), "r"(a[1]), "r"(a[2]), "r"(a[3]), "r"(b0), "r"(b1), "f"(z));
}

// B stage offset for (code row 0..255, 16B unit j 0..7); full 128B row
__device__ __forceinline__ u32 b_off(int row, int j) {
    return (u32)(row * 128 + ((j ^ (row & 7)) * 16));
}

__global__ void __launch_bounds__(NTHREADS, 1) mma_argmax_kernel(
        const float* __restrict__ x,
        const float* __restrict__ w,
        float* __restrict__ out) {
    extern __shared__ char dsm[];
    u64* best = (u64*)(dsm + SM_BEST);

    int tid  = threadIdx.x;
    int warp = tid >> 5;
    int lane = tid & 31;
    int r    = lane >> 2;     // 0..7
    int tg   = lane & 3;      // 0..3
    int warpM = warp >> 2;    // 0..3
    int warpN = warp & 3;     // 0..3
    int t0   = blockIdx.x * BLK_T;

    u32 sbase = (u32)__cvta_generic_to_shared(dsm);

    if (tid < BLK_T) best[tid] = packkey(-3e38f, 0);

    // ---- load A: 128 tokens x 512 d fp32 -> bf16, swizzled ----
#pragma unroll
    for (int i = 0; i < 16; i++) {
        int f   = i * NTHREADS + tid;     // 0..8191 16B units (8 bf16 each)
        int row = f >> 6;
        int j   = f & 63;
        const float* src = &x[(size_t)(t0 + row) * D + j * 8];
        float4 a = *(const float4*)src;
        float4 b = *(const float4*)(src + 4);
        uint4 v;
        v.x = pack_bf16(a.x, a.y);
        v.y = pack_bf16(a.z, a.w);
        v.z = pack_bf16(b.x, b.y);
        v.w = pack_bf16(b.z, b.w);
        *(uint4*)(dsm + SM_A + row * 1024 + ((j ^ (row & 7)) * 16)) = v;
    }

    // ---- prime B pipeline: chunks g=0,1 (tile 0, d-chunks 0,1) ----
#pragma unroll
    for (int pg = 0; pg < 2; pg++) {
#pragma unroll
        for (int p = 0; p < 4; p++) {
            int f = p * NTHREADS + tid;   // 0..2047 16B units
            int row = f >> 3, j = f & 7;
            cp16(sbase + SM_B + pg * B_STAGE + b_off(row, j),
                 &g_wb[(size_t)row * D + pg * 64 + j * 8]);
        }
        cp_commit();
    }

    // ldmatrix lane components
    int a_rowl = (lane & 15);             // + warpM*32 + mi*16
    int a_jl   = (lane >> 4);             // + c*8 + s*2
    int a_xor  = (lane & 7);              // (R & 7)
    int b_rowl = warpN * 64 + (lane & 7) + ((lane & 16) ? 8 : 0);
    int b_jl   = ((lane >> 3) & 1);       // + s*2

    float acc[2][8][4];
#pragma unroll
    for (int mi = 0; mi < 2; mi++)
#pragma unroll
        for (int ni = 0; ni < 8; ni++)
#pragma unroll
            for (int e = 0; e < 4; e++) acc[mi][ni][e] = 0.f;

    for (int g = 0; g < GTOT; g++) {
        int c = g & 7;                    // d-chunk within tile (64 d each)

        // wait own copies of chunk g (pending {g, g+1} -> leave 1)
        if (g < GTOT - 1) cp_wait<1>();
        else cp_wait<0>();
        __syncthreads();   // chunk-g B visible; also publishes prev tile's atomicMax

        // ---- deferred candidate collection for the PREVIOUS tile ----
        // (acc still holds prev tile's scores; best[] finalized by the sync)
        if (c == 0 && g > 0) {
            int pkt = ((g >> 3) - 1) * 256;
#pragma unroll
            for (int mi = 0; mi < 2; mi++) {
#pragma unroll
                for (int h = 0; h < 2; h++) {
                    int lt = warpM * 32 + mi * 16 + h * 8 + r;
                    float thr = unpackval(best[lt]) - MARGIN;
                    int token = t0 + lt;
#pragma unroll
                    for (int ni = 0; ni < 8; ni++) {
                        int k0 = pkt + warpN * 64 + ni * 8 + 2 * tg;
#pragma unroll
                        for (int e = 0; e < 2; e++) {
                            if (acc[mi][ni][h * 2 + e] >= thr) {
                                int pos = atomicAdd(&g_ccnt[token], 1);
                                if (pos < CAP) g_cand[token * CAP + pos] = k0 + e;
                            }
                        }
                    }
                }
            }
        }

        // ---- compute chunk g (64 d = 4 s-steps) from stage g%3 ----
        u32 bstage = sbase + SM_B + (g % 3) * B_STAGE;
#pragma unroll
        for (int s = 0; s < 4; s++) {
            int aj = c * 8 + s * 2 + a_jl;
            u32 af[2][4];
#pragma unroll
            for (int mi = 0; mi < 2; mi++) {
                int R = warpM * 32 + mi * 16 + a_rowl;
                u32 addr = sbase + SM_A + R * 1024 + ((aj ^ a_xor) * 16);
                ldsm4(af[mi][0], af[mi][1], af[mi][2], af[mi][3], addr);
            }
            int bj = s * 2 + b_jl;
#pragma unroll
            for (int nn = 0; nn < 4; nn++) {
                u32 b0, b1, b2, b3;
                int row = b_rowl + nn * 16;
                ldsm4(b0, b1, b2, b3, bstage + b_off(row, bj));
                if (s == 0 && c == 0) {
                    // first s-step of a tile: overwrite acc (c operand = 0)
#pragma unroll
                    for (int mi = 0; mi < 2; mi++) {
                        mma_zero(acc[mi][nn*2],     af[mi], b0, b1);
                        mma_zero(acc[mi][nn*2 + 1], af[mi], b2, b3);
                    }
                } else {
#pragma unroll
                    for (int mi = 0; mi < 2; mi++) {
                        mma_acc(acc[mi][nn*2],     af[mi], b0, b1);
                        mma_acc(acc[mi][nn*2 + 1], af[mi], b2, b3);
                    }
                }
            }
        }

        // ---- issue chunk g+2 into stage (g+2)%3 == (g-1)%3 (freed by the sync)
        if (g + 2 < GTOT) {
            int ng = g + 2;
            int nkt = (ng >> 3) * 256, nc = ng & 7;
            u32 dst = sbase + SM_B + (ng % 3) * B_STAGE;
#pragma unroll
            for (int p = 0; p < 4; p++) {
                int f = p * NTHREADS + tid;
                int row = f >> 3, j = f & 7;
                cp16(dst + b_off(row, j),
                     &g_wb[(size_t)(nkt + row) * D + nc * 64 + j * 8]);
            }
            cp_commit();
        }

        // ---- tile complete: fold running max, publish (barrier-free) ----
        if (c == 7) {
            int kt = (g >> 3) * 256;
#pragma unroll
            for (int mi = 0; mi < 2; mi++) {
#pragma unroll
                for (int h = 0; h < 2; h++) {
                    float bv = -3e38f; int bk = 0;
#pragma unroll
                    for (int ni = 0; ni < 8; ni++) {
                        int k0 = kt + warpN * 64 + ni * 8 + 2 * tg;
                        float v0 = acc[mi][ni][h * 2 + 0];
                        float v1 = acc[mi][ni][h * 2 + 1];
                        if (v0 > bv) { bv = v0; bk = k0; }
                        if (v1 > bv) { bv = v1; bk = k0 + 1; }
                    }
                    u64 key = packkey(bv, bk);
                    u64 o1 = __shfl_xor_sync(0xffffffffu, key, 1);
                    if (o1 > key) key = o1;
                    u64 o2 = __shfl_xor_sync(0xffffffffu, key, 2);
                    if (o2 > key) key = o2;
                    if (tg == 0)
                        atomicMax(&best[warpM * 32 + mi * 16 + h * 8 + r], key);
                }
            }
        }
    }

    // ---- final tile's collection (needs one more publish barrier) ----
    __syncthreads();
    {
        int pkt = (GTOT / 8 - 1) * 256;   // last tile's code base
#pragma unroll
        for (int mi = 0; mi < 2; mi++) {
#pragma unroll
            for (int h = 0; h < 2; h++) {
                int lt = warpM * 32 + mi * 16 + h * 8 + r;
                float thr = unpackval(best[lt]) - MARGIN;
                int token = t0 + lt;
#pragma unroll
                for (int ni = 0; ni < 8; ni++) {
                    int k0 = pkt + warpN * 64 + ni * 8 + 2 * tg;
#pragma unroll
                    for (int e = 0; e < 2; e++) {
                        if (acc[mi][ni][h * 2 + e] >= thr) {
                            int pos = atomicAdd(&g_ccnt[token], 1);
                            if (pos < CAP) g_cand[token * CAP + pos] = k0 + e;
                        }
                    }
                }
            }
        }
    }

    // =======================================================================
    // fused tail: exact fp32 rescore + gather/loss/emaw, 8 tokens per warp
    // =======================================================================
    __syncthreads();
    float* out_idx = out + OFF_IDX;

    for (int i = 0; i < 8; i++) {
        int lt = warp * 8 + i;
        int token = t0 + lt;
        const float* xr = x + (size_t)token * D;

        float4 xv[4];
#pragma unroll
        for (int c = 0; c < 4; c++)
            xv[c] = *(const float4*)&xr[lane * 4 + c * 128];

        int cnt = g_ccnt[token];
        float bestv = -3e38f;
        int   bk    = K;

        if (cnt <= CAP) {
            for (int j = 0; j < cnt; j++) {
                int k = g_cand[token * CAP + j];
                float s = 0.f;
#pragma unroll
                for (int c = 0; c < 4; c++) {
                    float4 wv = *(const float4*)&w[(size_t)k * D + lane * 4 + c * 128];
                    s += xv[c].x * wv.x + xv[c].y * wv.y + xv[c].z * wv.z + xv[c].w * wv.w;
                }
#pragma unroll
                for (int o = 16; o; o >>= 1) s += __shfl_xor_sync(0xffffffffu, s, o);
                s *= g_cbnorm[k];
                if (s > bestv || (s == bestv && k < bk)) { bestv = s; bk = k; }
            }
        } else {
            // overflow fallback: exact scan of all codes
            for (int k = 0; k < K; k++) {
                float s = 0.f;
#pragma unroll
                for (int c = 0; c < 4; c++) {
                    float4 wv = *(const float4*)&w[(size_t)k * D + lane * 4 + c * 128];
                    s += xv[c].x * wv.x + xv[c].y * wv.y + xv[c].z * wv.z + xv[c].w * wv.w;
                }
#pragma unroll
                for (int o = 16; o; o >>= 1) s += __shfl_xor_sync(0xffffffffu, s, o);
                s *= g_cbnorm[k];
                if (s > bestv || (s == bestv && k < bk)) { bestv = s; bk = k; }
            }
        }

        // gather + straight-through + loss + emaw scatter
        const float* wr = w + (size_t)bk * D;
        float* q    = out + OFF_Q + (size_t)token * D;
        float* emaw = out + OFF_EMAW + (size_t)bk * D;

        float lsum = 0.f;
#pragma unroll
        for (int c = 0; c < 4; c++) {
            int d = lane * 4 + c * 128;
            float4 wv = *(const float4*)&wr[d];
            float4 qv;
            qv.x = xv[c].x + (wv.x - xv[c].x);
            qv.y = xv[c].y + (wv.y - xv[c].y);
            qv.z = xv[c].z + (wv.z - xv[c].z);
            qv.w = xv[c].w + (wv.w - xv[c].w);
            *(float4*)&q[d] = qv;
            float d0 = wv.x - xv[c].x, d1 = wv.y - xv[c].y;
            float d2 = wv.z - xv[c].z, d3 = wv.w - xv[c].w;
            lsum += d0 * d0 + d1 * d1 + d2 * d2 + d3 * d3;
            atomicAdd(&emaw[d + 0], OMD * xv[c].x);
            atomicAdd(&emaw[d + 1], OMD * xv[c].y);
            atomicAdd(&emaw[d + 2], OMD * xv[c].z);
            atomicAdd(&emaw[d + 3], OMD * xv[c].w);
        }
#pragma unroll
        for (int o = 16; o; o >>= 1) lsum += __shfl_xor_sync(0xffffffffu, lsum, o);
        if (lane == 0) {
            atomicAdd(&g_loss, lsum);
            out_idx[token] = (float)bk;
            atomicAdd(&g_counts[bk], 1.0f);
        }
    }
}

// ---------------------------------------------------------------------------
// k4: cluster-size EMA pre-values + global sum
// ---------------------------------------------------------------------------
__global__ void __launch_bounds__(256) cs_kernel(const float* __restrict__ ecs) {
    __shared__ float red[256];
    int k = blockIdx.x * 256 + threadIdx.x;
    float v = ecs[k] * DECAYC + OMD * g_counts[k];
    g_cs_pre[k] = v;
    red[threadIdx.x] = v;
    __syncthreads();
    for (int s = 128; s; s >>= 1) {
        if (threadIdx.x < s) red[threadIdx.x] += red[threadIdx.x + s];
        __syncthreads();
    }
    if (threadIdx.x == 0) atomicAdd(&g_sum, red[0]);
}

// ---------------------------------------------------------------------------
// k5: finalize new_cs, new_weight, loss mean
// ---------------------------------------------------------------------------
__global__ void __launch_bounds__(256) finalize_kernel(float* __restrict__ out) {
    int gid = blockIdx.x * 256 + threadIdx.x;
    if (gid == 0) out[OFF_LOSS] = g_loss * (1.0f / ((float)N_TOK * (float)D));

    int k  = gid >> 7;
    int d4 = gid & 127;
    float n  = g_sum;
    float cs = (g_cs_pre[k] + EPSC) / (n + (float)K * EPSC) * n;
    if (d4 == 0) out[OFF_CS + k] = cs;

    size_t base = (size_t)k * D + d4 * 4;
#pragma unroll
    for (int q = 0; q < 4; q++) {
        float e = out[OFF_EMAW + base + q];
        out[OFF_W + base + q] = e / cs;
    }
}

// ---------------------------------------------------------------------------
extern "C" void kernel_launch(void* const* d_in, const int* in_sizes, int n_in,
                              void* d_out, int out_size) {
    const float* x    = (const float*)d_in[0];
    const float* w    = (const float*)d_in[1];
    const float* ecs  = (const float*)d_in[2];
    const float* emaw = (const float*)d_in[3];
    float* out = (float*)d_out;

    cudaFuncSetAttribute(mma_argmax_kernel,
                         cudaFuncAttributeMaxDynamicSharedMemorySize, SMEM_BYTES);

    setup_kernel<<<5120, 256>>>(w, emaw, out);
    mma_argmax_kernel<<<N_TOK / BLK_T, NTHREADS, SMEM_BYTES>>>(x, w, out);
    cs_kernel<<<K / 256, 256>>>(ecs);
    finalize_kernel<<<(K * D / 4) / 256, 256>>>(out);
}

// round 15
// speedup vs baseline: 8.0751x; 1.0110x over previous
#include <cuda_runtime.h>
#include <cuda_bf16.h>
#include <cstdint>

#define N_TOK 16384
#define D 512
#define K 8192

typedef unsigned int u32;
typedef unsigned long long u64;

constexpr float DECAYC = 0.99f;
constexpr float OMD = (float)(1.0 - 0.99);
constexpr float EPSC = 1e-5f;
constexpr float MARGIN = 0.15f;
#define CAP 32

// output layout (concatenated, float32)
#define OFF_Q    0
#define OFF_LOSS 8388608
#define OFF_IDX  8388609
#define OFF_CS   8404993
#define OFF_EMAW 8413185
#define OFF_W    12607489

// device scratch
__device__ float g_cbnorm[K];
__device__ float g_counts[K];
__device__ float g_cs_pre[K];
__device__ float g_loss;
__device__ float g_sum;
// chunk-major, pre-swizzled normalized codebook:
// chunk g (0..255) covers codes [ (g>>3)*256, +256 ), dims [ (g&7)*64, +64 )
// byte (row,j16) at g*32768 + row*128 + ((j^(row&7))*16)
__device__ unsigned char g_wb[K * D * 2];
__device__ int g_ccnt[N_TOK];
__device__ int g_cand[N_TOK * CAP];

__device__ __forceinline__ u64 packkey(float v, int k) {
    u32 b = __float_as_uint(v);
    b = (b & 0x80000000u) ? ~b : (b | 0x80000000u);
    return ((u64)b << 32) | (u32)k;
}
__device__ __forceinline__ float unpackval(u64 key) {
    u32 b = (u32)(key >> 32);
    b = (b & 0x80000000u) ? (b & 0x7FFFFFFFu) : ~b;
    return __uint_as_float(b);
}
__device__ __forceinline__ u32 pack_bf16(float a, float b) {
    __nv_bfloat162 h = __floats2bfloat162_rn(a, b);
    return *(u32*)&h;
}

// ---------------------------------------------------------------------------
// mbarrier + bulk-copy helpers (sm_90 baseline PTX)
// ---------------------------------------------------------------------------
__device__ __forceinline__ void mbar_init(u32 addr, u32 count) {
    asm volatile("mbarrier.init.shared.b64 [%0], %1;" :: "r"(addr), "r"(count) : "memory");
}
__device__ __forceinline__ void mbar_expect(u32 addr, u32 bytes) {
    asm volatile("mbarrier.arrive.expect_tx.shared.b64 _, [%0], %1;"
                 :: "r"(addr), "r"(bytes) : "memory");
}
__device__ __forceinline__ void mbar_wait(u32 addr, u32 phase) {
    asm volatile(
        "{\n\t.reg .pred P;\n"
        "W_%=:\n\t"
        "mbarrier.try_wait.parity.acquire.cta.shared::cta.b64 P, [%0], %1, 0x989680;\n\t"
        "@P bra.uni D_%=;\n\t"
        "bra.uni W_%=;\n"
        "D_%=:\n\t}"
        :: "r"(addr), "r"(phase) : "memory");
}
__device__ __forceinline__ void bulk_g2s(u32 dst_smem, const void* src, u32 bytes, u32 mbar) {
    asm volatile(
        "cp.async.bulk.shared::cluster.global.mbarrier::complete_tx::bytes "
        "[%0], [%1], %2, [%3];"
        :: "r"(dst_smem), "l"(src), "r"(bytes), "r"(mbar) : "memory");
}

// ---------------------------------------------------------------------------
// k0 (merged): [0,1024) codebook norms + chunk-major pre-swizzled bf16 write
//              + zero accum; [1024,5120) ema_w*DECAY
// ---------------------------------------------------------------------------
__global__ void __launch_bounds__(256) setup_kernel(const float* __restrict__ w,
                                                    const float* __restrict__ emaw,
                                                    float* __restrict__ out) {
    int bid = blockIdx.x;
    if (bid < 1024) {
        int gid  = bid * 256 + threadIdx.x;
        int wid  = gid >> 5;          // code row 0..8191
        int lane = threadIdx.x & 31;

        const float* row = w + (size_t)wid * D;
        float s = 0.f;
#pragma unroll
        for (int c = 0; c < 4; c++) {
            float4 v = *(const float4*)&row[lane * 4 + c * 128];
            s += v.x * v.x + v.y * v.y + v.z * v.z + v.w * v.w;
        }
#pragma unroll
        for (int o = 16; o; o >>= 1) s += __shfl_xor_sync(0xffffffffu, s, o);
        float cbn = rsqrtf(s + 1e-12f);
        if (lane == 0) g_cbnorm[wid] = cbn;

        // write normalized bf16 into chunk-major pre-swizzled layout
        int tile = wid >> 8;          // 0..31
        int rin  = wid & 255;
#pragma unroll
        for (int uu = 0; uu < 2; uu++) {
            int u  = lane * 2 + uu;   // 16B unit 0..63 within the code row
            int cc = u >> 3, j = u & 7;
            const float* src = &row[cc * 64 + j * 8];
            float4 a = *(const float4*)src;
            float4 b = *(const float4*)(src + 4);
            uint4 pv;
            pv.x = pack_bf16(a.x * cbn, a.y * cbn);
            pv.y = pack_bf16(a.z * cbn, a.w * cbn);
            pv.z = pack_bf16(b.x * cbn, b.y * cbn);
            pv.w = pack_bf16(b.z * cbn, b.w * cbn);
            size_t goff = ((size_t)(tile * 8 + cc) << 15)
                        + (size_t)(rin * 128 + ((j ^ (rin & 7)) * 16));
            *(uint4*)(g_wb + goff) = pv;
        }

        if (gid < K) g_counts[gid] = 0.f;
        if (gid < N_TOK) g_ccnt[gid] = 0;
        if (gid == 0) { g_loss = 0.f; g_sum = 0.f; }
    } else {
        int gid = (bid - 1024) * 256 + threadIdx.x;
        float4 v = *(const float4*)&emaw[gid * 4];
        float* o = out + OFF_EMAW + (size_t)gid * 4;
        o[0] = v.x * DECAYC;
        o[1] = v.y * DECAYC;
        o[2] = v.z * DECAYC;
        o[3] = v.w * DECAYC;
    }
}

// ---------------------------------------------------------------------------
// k1: bf16 mma.sync argmax GEMM + fused rescore/gather tail.
// 128 tokens/CTA, 512 threads (16 warps, 4M x 4N), warp tile 32x64.
// B chunks arrive via single cp.async.bulk (32KB) + mbarrier per chunk —
// eliminates the LDGSTS issue wall. Loop: mbar-wait -> sync ->
// collect(prev tile) -> issue bulk(g+2) -> compute -> fold.
// ---------------------------------------------------------------------------
#define BLK_T 128
#define NTHREADS 512
#define SM_BEST 0
#define SM_MBAR 1024
#define SM_A    2048
#define SM_B    (SM_A + 131072)               // 133120
#define B_STAGE 32768
#define SMEM_BYTES (SM_B + 3 * B_STAGE)       // 231424
#define GTOT 256                               // 32 tiles * 8 chunks (64d each)

__device__ __forceinline__ void ldsm4(u32& r0, u32& r1, u32& r2, u32& r3, u32 addr) {
    asm volatile("ldmatrix.sync.aligned.m8n8.x4.shared.b16 {%0,%1,%2,%3}, [%4];\n"
                 : "=r"(r0), "=r"(r1), "=r"(r2), "=r"(r3) : "r"(addr));
}

__device__ __forceinline__ void mma_acc(float* d, const u32* a, u32 b0, u32 b1) {
    asm volatile(
        "mma.sync.aligned.m16n8k16.row.col.f32.bf16.bf16.f32 "
        "{%0,%1,%2,%3}, {%4,%5,%6,%7}, {%8,%9}, {%0,%1,%2,%3};\n"
        : "+f"(d[0]), "+f"(d[1]), "+f"(d[2]), "+f"(d[3])
        : "r"(a[0]), "r"(a[1]), "r"(a[2]), "r"(a[3]), "r"(b0), "r"(b1));
}
__device__ __forceinline__ void mma_zero(float* d, const u32* a, u32 b0, u32 b1) {
    float z = 0.f;
    asm volatile(
        "mma.sync.aligned.m16n8k16.row.col.f32.bf16.bf16.f32 "
        "{%0,%1,%2,%3}, {%4,%5,%6,%7}, {%8,%9}, {%10,%10,%10,%10};\n"
        : "=f"(d[0]), "=f"(d[1]), "=f"(d[2]), "=f"(d[3])
        : "r"(a[0]), "r"(a[1]), "r"(a[2]), "r"(a[3]), "r"(b0), "r"(b1), "f"(z));
}

// B stage offset for (code row 0..255, 16B unit j 0..7); full 128B row
__device__ __forceinline__ u32 b_off(int row, int j) {
    return (u32)(row * 128 + ((j ^ (row & 7)) * 16));
}

__global__ void __launch_bounds__(NTHREADS, 1) mma_argmax_kernel(
        const float* __restrict__ x,
        const float* __restrict__ w,
        float* __restrict__ out) {
    extern __shared__ char dsm[];
    u64* best = (u64*)(dsm + SM_BEST);

    int tid  = threadIdx.x;
    int warp = tid >> 5;
    int lane = tid & 31;
    int r    = lane >> 2;     // 0..7
    int tg   = lane & 3;      // 0..3
    int warpM = warp >> 2;    // 0..3
    int warpN = warp & 3;     // 0..3
    int t0   = blockIdx.x * BLK_T;

    u32 sbase = (u32)__cvta_generic_to_shared(dsm);
    u32 mb = sbase + SM_MBAR;

    if (tid < BLK_T) best[tid] = packkey(-3e38f, 0);
    if (tid == 0) {
        mbar_init(mb + 0, 1);
        mbar_init(mb + 8, 1);
        mbar_init(mb + 16, 1);
    }

    // ---- load A: 128 tokens x 512 d fp32 -> bf16, swizzled ----
#pragma unroll
    for (int i = 0; i < 16; i++) {
        int f   = i * NTHREADS + tid;     // 0..8191 16B units (8 bf16 each)
        int row = f >> 6;
        int j   = f & 63;
        const float* src = &x[(size_t)(t0 + row) * D + j * 8];
        float4 a = *(const float4*)src;
        float4 b = *(const float4*)(src + 4);
        uint4 v;
        v.x = pack_bf16(a.x, a.y);
        v.y = pack_bf16(a.z, a.w);
        v.z = pack_bf16(b.x, b.y);
        v.w = pack_bf16(b.z, b.w);
        *(uint4*)(dsm + SM_A + row * 1024 + ((j ^ (row & 7)) * 16)) = v;
    }
    __syncthreads();   // mbars initialized; A visible before any compute

    // ---- prime: bulk-issue chunks 0,1 ----
    if (tid == 0) {
#pragma unroll
        for (int pg = 0; pg < 2; pg++) {
            mbar_expect(mb + pg * 8, B_STAGE);
            bulk_g2s(sbase + SM_B + pg * B_STAGE, g_wb + ((size_t)pg << 15),
                     B_STAGE, mb + pg * 8);
        }
    }

    // ldmatrix lane components
    int a_rowl = (lane & 15);             // + warpM*32 + mi*16
    int a_jl   = (lane >> 4);             // + c*8 + s*2
    int a_xor  = (lane & 7);              // (R & 7)
    int b_rowl = warpN * 64 + (lane & 7) + ((lane & 16) ? 8 : 0);
    int b_jl   = ((lane >> 3) & 1);       // + s*2

    float acc[2][8][4];
#pragma unroll
    for (int mi = 0; mi < 2; mi++)
#pragma unroll
        for (int ni = 0; ni < 8; ni++)
#pragma unroll
            for (int e = 0; e < 4; e++) acc[mi][ni][e] = 0.f;

    u32 ph0 = 0, ph1 = 0, ph2 = 0;

    for (int g = 0; g < GTOT; g++) {
        int c = g & 7;                    // d-chunk within tile (64 d each)
        int st = g % 3;

        // wait chunk g's bulk copy
        if (st == 0) { mbar_wait(mb + 0, ph0); ph0 ^= 1; }
        else if (st == 1) { mbar_wait(mb + 8, ph1); ph1 ^= 1; }
        else { mbar_wait(mb + 16, ph2); ph2 ^= 1; }
        __syncthreads();   // all threads past compute g-1; publishes prev atomicMax

        // ---- deferred candidate collection for the PREVIOUS tile ----
        if (c == 0 && g > 0) {
            int pkt = ((g >> 3) - 1) * 256;
#pragma unroll
            for (int mi = 0; mi < 2; mi++) {
#pragma unroll
                for (int h = 0; h < 2; h++) {
                    int lt = warpM * 32 + mi * 16 + h * 8 + r;
                    float thr = unpackval(best[lt]) - MARGIN;
                    int token = t0 + lt;
#pragma unroll
                    for (int ni = 0; ni < 8; ni++) {
                        int k0 = pkt + warpN * 64 + ni * 8 + 2 * tg;
#pragma unroll
                        for (int e = 0; e < 2; e++) {
                            if (acc[mi][ni][h * 2 + e] >= thr) {
                                int pos = atomicAdd(&g_ccnt[token], 1);
                                if (pos < CAP) g_cand[token * CAP + pos] = k0 + e;
                            }
                        }
                    }
                }
            }
        }

        // ---- issue bulk for chunk g+2 into stage (g+2)%3 == (g-1)%3 ----
        if (tid == 0 && g + 2 < GTOT) {
            int ng = g + 2, nst = ng % 3;
            mbar_expect(mb + nst * 8, B_STAGE);
            bulk_g2s(sbase + SM_B + nst * B_STAGE, g_wb + ((size_t)ng << 15),
                     B_STAGE, mb + nst * 8);
        }

        // ---- compute chunk g (64 d = 4 s-steps) from stage st ----
        u32 bstage = sbase + SM_B + st * B_STAGE;
#pragma unroll
        for (int s = 0; s < 4; s++) {
            int aj = c * 8 + s * 2 + a_jl;
            u32 af[2][4];
#pragma unroll
            for (int mi = 0; mi < 2; mi++) {
                int R = warpM * 32 + mi * 16 + a_rowl;
                u32 addr = sbase + SM_A + R * 1024 + ((aj ^ a_xor) * 16);
                ldsm4(af[mi][0], af[mi][1], af[mi][2], af[mi][3], addr);
            }
            int bj = s * 2 + b_jl;
#pragma unroll
            for (int nn = 0; nn < 4; nn++) {
                u32 b0, b1, b2, b3;
                int row = b_rowl + nn * 16;
                ldsm4(b0, b1, b2, b3, bstage + b_off(row, bj));
                if (s == 0 && c == 0) {
#pragma unroll
                    for (int mi = 0; mi < 2; mi++) {
                        mma_zero(acc[mi][nn*2],     af[mi], b0, b1);
                        mma_zero(acc[mi][nn*2 + 1], af[mi], b2, b3);
                    }
                } else {
#pragma unroll
                    for (int mi = 0; mi < 2; mi++) {
                        mma_acc(acc[mi][nn*2],     af[mi], b0, b1);
                        mma_acc(acc[mi][nn*2 + 1], af[mi], b2, b3);
                    }
                }
            }
        }

        // ---- tile complete: fold running max, publish (barrier-free) ----
        if (c == 7) {
            int kt = (g >> 3) * 256;
#pragma unroll
            for (int mi = 0; mi < 2; mi++) {
#pragma unroll
                for (int h = 0; h < 2; h++) {
                    float bv = -3e38f; int bk = 0;
#pragma unroll
                    for (int ni = 0; ni < 8; ni++) {
                        int k0 = kt + warpN * 64 + ni * 8 + 2 * tg;
                        float v0 = acc[mi][ni][h * 2 + 0];
                        float v1 = acc[mi][ni][h * 2 + 1];
                        if (v0 > bv) { bv = v0; bk = k0; }
                        if (v1 > bv) { bv = v1; bk = k0 + 1; }
                    }
                    u64 key = packkey(bv, bk);
                    u64 o1 = __shfl_xor_sync(0xffffffffu, key, 1);
                    if (o1 > key) key = o1;
                    u64 o2 = __shfl_xor_sync(0xffffffffu, key, 2);
                    if (o2 > key) key = o2;
                    if (tg == 0)
                        atomicMax(&best[warpM * 32 + mi * 16 + h * 8 + r], key);
                }
            }
        }
    }

    // ---- final tile's collection (one more publish barrier) ----
    __syncthreads();
    {
        int pkt = (GTOT / 8 - 1) * 256;   // last tile's code base
#pragma unroll
        for (int mi = 0; mi < 2; mi++) {
#pragma unroll
            for (int h = 0; h < 2; h++) {
                int lt = warpM * 32 + mi * 16 + h * 8 + r;
                float thr = unpackval(best[lt]) - MARGIN;
                int token = t0 + lt;
#pragma unroll
                for (int ni = 0; ni < 8; ni++) {
                    int k0 = pkt + warpN * 64 + ni * 8 + 2 * tg;
#pragma unroll
                    for (int e = 0; e < 2; e++) {
                        if (acc[mi][ni][h * 2 + e] >= thr) {
                            int pos = atomicAdd(&g_ccnt[token], 1);
                            if (pos < CAP) g_cand[token * CAP + pos] = k0 + e;
                        }
                    }
                }
            }
        }
    }

    // =======================================================================
    // fused tail: exact fp32 rescore + gather/loss/emaw, 8 tokens per warp
    // =======================================================================
    __syncthreads();
    float* out_idx = out + OFF_IDX;

    for (int i = 0; i < 8; i++) {
        int lt = warp * 8 + i;
        int token = t0 + lt;
        const float* xr = x + (size_t)token * D;

        float4 xv[4];
#pragma unroll
        for (int c = 0; c < 4; c++)
            xv[c] = *(const float4*)&xr[lane * 4 + c * 128];

        int cnt = g_ccnt[token];
        float bestv = -3e38f;
        int   bk    = K;

        if (cnt <= CAP) {
            for (int j = 0; j < cnt; j++) {
                int k = g_cand[token * CAP + j];
                float s = 0.f;
#pragma unroll
                for (int c = 0; c < 4; c++) {
                    float4 wv = *(const float4*)&w[(size_t)k * D + lane * 4 + c * 128];
                    s += xv[c].x * wv.x + xv[c].y * wv.y + xv[c].z * wv.z + xv[c].w * wv.w;
                }
#pragma unroll
                for (int o = 16; o; o >>= 1) s += __shfl_xor_sync(0xffffffffu, s, o);
                s *= g_cbnorm[k];
                if (s > bestv || (s == bestv && k < bk)) { bestv = s; bk = k; }
            }
        } else {
            // overflow fallback: exact scan of all codes
            for (int k = 0; k < K; k++) {
                float s = 0.f;
#pragma unroll
                for (int c = 0; c < 4; c++) {
                    float4 wv = *(const float4*)&w[(size_t)k * D + lane * 4 + c * 128];
                    s += xv[c].x * wv.x + xv[c].y * wv.y + xv[c].z * wv.z + xv[c].w * wv.w;
                }
#pragma unroll
                for (int o = 16; o; o >>= 1) s += __shfl_xor_sync(0xffffffffu, s, o);
                s *= g_cbnorm[k];
                if (s > bestv || (s == bestv && k < bk)) { bestv = s; bk = k; }
            }
        }

        // gather + straight-through + loss + emaw scatter
        const float* wr = w + (size_t)bk * D;
        float* q    = out + OFF_Q + (size_t)token * D;
        float* emaw = out + OFF_EMAW + (size_t)bk * D;

        float lsum = 0.f;
#pragma unroll
        for (int c = 0; c < 4; c++) {
            int d = lane * 4 + c * 128;
            float4 wv = *(const float4*)&wr[d];
            float4 qv;
            qv.x = xv[c].x + (wv.x - xv[c].x);
            qv.y = xv[c].y + (wv.y - xv[c].y);
            qv.z = xv[c].z + (wv.z - xv[c].z);
            qv.w = xv[c].w + (wv.w - xv[c].w);
            *(float4*)&q[d] = qv;
            float d0 = wv.x - xv[c].x, d1 = wv.y - xv[c].y;
            float d2 = wv.z - xv[c].z, d3 = wv.w - xv[c].w;
            lsum += d0 * d0 + d1 * d1 + d2 * d2 + d3 * d3;
            atomicAdd(&emaw[d + 0], OMD * xv[c].x);
            atomicAdd(&emaw[d + 1], OMD * xv[c].y);
            atomicAdd(&emaw[d + 2], OMD * xv[c].z);
            atomicAdd(&emaw[d + 3], OMD * xv[c].w);
        }
#pragma unroll
        for (int o = 16; o; o >>= 1) lsum += __shfl_xor_sync(0xffffffffu, lsum, o);
        if (lane == 0) {
            atomicAdd(&g_loss, lsum);
            out_idx[token] = (float)bk;
            atomicAdd(&g_counts[bk], 1.0f);
        }
    }
}

// ---------------------------------------------------------------------------
// k4: cluster-size EMA pre-values + global sum
// ---------------------------------------------------------------------------
__global__ void __launch_bounds__(256) cs_kernel(const float* __restrict__ ecs) {
    __shared__ float red[256];
    int k = blockIdx.x * 256 + threadIdx.x;
    float v = ecs[k] * DECAYC + OMD * g_counts[k];
    g_cs_pre[k] = v;
    red[threadIdx.x] = v;
    __syncthreads();
    for (int s = 128; s; s >>= 1) {
        if (threadIdx.x < s) red[threadIdx.x] += red[threadIdx.x + s];
        __syncthreads();
    }
    if (threadIdx.x == 0) atomicAdd(&g_sum, red[0]);
}

// ---------------------------------------------------------------------------
// k5: finalize new_cs, new_weight, loss mean
// ---------------------------------------------------------------------------
__global__ void __launch_bounds__(256) finalize_kernel(float* __restrict__ out) {
    int gid = blockIdx.x * 256 + threadIdx.x;
    if (gid == 0) out[OFF_LOSS] = g_loss * (1.0f / ((float)N_TOK * (float)D));

    int k  = gid >> 7;
    int d4 = gid & 127;
    float n  = g_sum;
    float cs = (g_cs_pre[k] + EPSC) / (n + (float)K * EPSC) * n;
    if (d4 == 0) out[OFF_CS + k] = cs;

    size_t base = (size_t)k * D + d4 * 4;
#pragma unroll
    for (int q = 0; q < 4; q++) {
        float e = out[OFF_EMAW + base + q];
        out[OFF_W + base + q] = e / cs;
    }
}

// ---------------------------------------------------------------------------
extern "C" void kernel_launch(void* const* d_in, const int* in_sizes, int n_in,
                              void* d_out, int out_size) {
    const float* x    = (const float*)d_in[0];
    const float* w    = (const float*)d_in[1];
    const float* ecs  = (const float*)d_in[2];
    const float* emaw = (const float*)d_in[3];
    float* out = (float*)d_out;

    cudaFuncSetAttribute(mma_argmax_kernel,
                         cudaFuncAttributeMaxDynamicSharedMemorySize, SMEM_BYTES);

    setup_kernel<<<5120, 256>>>(w, emaw, out);
    mma_argmax_kernel<<<N_TOK / BLK_T, NTHREADS, SMEM_BYTES>>>(x, w, out);
    cs_kernel<<<K / 256, 256>>>(ecs);
    finalize_kernel<<<(K * D / 4) / 256, 256>>>(out);
}